// round 1
// baseline (speedup 1.0000x reference)
#include <cuda_runtime.h>
#include <cstdint>
#include <cstddef>

#define N_X 100000
#define N_C 100000
#define NE  500000
#define HID 128

typedef unsigned long long ull;

// Scratch (static __device__ arrays per allocation rules): 4 x 51.2 MB
__device__ float g_mxx [(size_t)N_X * HID];   // ex[:, H:2H]
__device__ float g_mxlx[(size_t)N_X * HID];   // ex[:, 2H:3H]
__device__ float g_mcx [(size_t)N_C * HID];   // ec[:, H:2H]
__device__ float g_agg [(size_t)N_X * HID];   // running aggregate (init = ex[:, :H])

__device__ __forceinline__ void fma2(ull& c, ull a, ull b) {
    asm("fma.rn.f32x2 %0, %1, %2, %0;" : "+l"(c) : "l"(a), "l"(b));
}
__device__ __forceinline__ float2 unpack2(ull v) {
    float2 r;
    asm("mov.b64 {%0, %1}, %2;" : "=f"(r.x), "=f"(r.y) : "l"(v));
    return r;
}

// ---------------- GEMM: C = relu?(A[M,K] @ B[K, gridDim.y*128] + bias) -------------
// BM=128, BN=128, BK=32, 256 threads, per-thread 8x8 via f32x2 (M-paired accs).
// A tile stored transposed [k][m] (pitch 132 for bank spread + 16B alignment).
// B tile stored duplicated {b,b} as u64 so no pack instructions in mainloop.

constexpr int BM = 128, BN = 128, BK = 32;
constexpr int APITCH = 132;
constexpr int SMEM_FLOATS = BK * APITCH + BK * 2 * BN;
constexpr int SMEM_BYTES  = SMEM_FLOATS * 4;   // 49664

template <int K, bool RELU>
__global__ __launch_bounds__(256, 2)
void gemm_kernel(const float* __restrict__ A, int M, int lda,
                 const float* __restrict__ B, int ldb,
                 const float* __restrict__ bias,
                 float* __restrict__ o0, float* __restrict__ o1, float* __restrict__ o2)
{
    extern __shared__ float smem[];
    float* sA = smem;                 // [BK][APITCH]  (transposed: [k][m])
    float* sB = smem + BK * APITCH;   // [BK][2*BN]    (value-duplicated pairs)

    const int tid = threadIdx.x;
    const int tx = tid & 15;          // n-position (16)
    const int ty = tid >> 4;          // m-position (16)
    const int rb = blockIdx.x * BM;
    const int cb = blockIdx.y * BN;

    ull acc[4][8];
#pragma unroll
    for (int i = 0; i < 4; i++)
#pragma unroll
        for (int j = 0; j < 8; j++) acc[i][j] = 0ULL;

#pragma unroll 1
    for (int kt = 0; kt < K; kt += BK) {
        // ---- load A tile (128 rows x 32 k), transpose into sA[k][m]
#pragma unroll
        for (int it = 0; it < 4; it++) {
            int r  = (tid >> 3) + 32 * it;
            int cc = (tid & 7) * 4;
            float4 v = make_float4(0.f, 0.f, 0.f, 0.f);
            if (rb + r < M)
                v = *reinterpret_cast<const float4*>(A + (size_t)(rb + r) * lda + kt + cc);
            sA[(cc + 0) * APITCH + r] = v.x;
            sA[(cc + 1) * APITCH + r] = v.y;
            sA[(cc + 2) * APITCH + r] = v.z;
            sA[(cc + 3) * APITCH + r] = v.w;
        }
        // ---- load B tile (32 k x 128 n), store duplicated {b,b}
#pragma unroll
        for (int it = 0; it < 4; it++) {
            int kk = (tid >> 5) + 8 * it;
            int nn = (tid & 31) * 4;
            float4 v = *reinterpret_cast<const float4*>(B + (size_t)(kt + kk) * ldb + cb + nn);
            *reinterpret_cast<float4*>(sB + kk * 2 * BN + 2 * nn)     = make_float4(v.x, v.x, v.y, v.y);
            *reinterpret_cast<float4*>(sB + kk * 2 * BN + 2 * nn + 4) = make_float4(v.z, v.z, v.w, v.w);
        }
        __syncthreads();

#pragma unroll 8
        for (int kk = 0; kk < BK; kk++) {
            const ulonglong2* ap  = reinterpret_cast<const ulonglong2*>(sA + kk * APITCH + ty * 8);
            ulonglong2 a01 = ap[0], a23 = ap[1];
            ull a[4] = {a01.x, a01.y, a23.x, a23.y};

            const ulonglong2* bp0 = reinterpret_cast<const ulonglong2*>(sB + kk * 2 * BN + tx * 8);
            const ulonglong2* bp1 = reinterpret_cast<const ulonglong2*>(sB + kk * 2 * BN + 128 + tx * 8);
            ulonglong2 b01 = bp0[0], b23 = bp0[1];
            ulonglong2 b45 = bp1[0], b67 = bp1[1];
            ull b[8] = {b01.x, b01.y, b23.x, b23.y, b45.x, b45.y, b67.x, b67.y};

#pragma unroll
            for (int mp = 0; mp < 4; mp++)
#pragma unroll
                for (int j = 0; j < 8; j++)
                    fma2(acc[mp][j], a[mp], b[j]);
        }
        __syncthreads();
    }

    float* o = (blockIdx.y == 0) ? o0 : ((blockIdx.y == 1) ? o1 : o2);

#pragma unroll
    for (int j = 0; j < 8; j++) {
        int col = (j < 4) ? (tx * 4 + j) : (64 + tx * 4 + (j - 4));
        float bb = bias[cb + col];
#pragma unroll
        for (int mp = 0; mp < 4; mp++) {
            int r0 = rb + ty * 8 + 2 * mp;
            float2 v = unpack2(acc[mp][j]);
            float v0 = v.x + bb;
            float v1 = v.y + bb;
            if (RELU) { v0 = fmaxf(v0, 0.f); v1 = fmaxf(v1, 0.f); }
            if (r0 < M)     o[(size_t)r0 * 128 + col]       = v0;
            if (r0 + 1 < M) o[(size_t)(r0 + 1) * 128 + col] = v1;
        }
    }
}

// ---------------- Scatter: one warp per edge, vector red.global --------------------
__global__ void scatter_kernel(const int* __restrict__ exx,
                               const int* __restrict__ exlx,
                               const int* __restrict__ ecx)
{
    int wid  = blockIdx.x * (blockDim.x >> 5) + (threadIdx.x >> 5);
    int lane = threadIdx.x & 31;
    if (wid >= 3 * NE) return;

    const float* src;
    int dst;
    if (wid < NE) {
        int e = wid;
        src = g_mxx + (size_t)exx[e] * HID;
        dst = exx[NE + e];
    } else if (wid < 2 * NE) {
        int e = wid - NE;
        src = g_mxlx + (size_t)exlx[NE + e] * HID;
        dst = exlx[e];
    } else {
        int e = wid - 2 * NE;
        src = g_mcx + (size_t)ecx[e] * HID;
        dst = ecx[NE + e];
    }

    float4 v = __ldg(reinterpret_cast<const float4*>(src) + lane);
    float* p = g_agg + (size_t)dst * HID + lane * 4;
    asm volatile("red.global.add.v4.f32 [%0], {%1, %2, %3, %4};"
                 :: "l"(p), "f"(v.x), "f"(v.y), "f"(v.z), "f"(v.w)
                 : "memory");
}

// ---------------- Launch -----------------------------------------------------------
extern "C" void kernel_launch(void* const* d_in, const int* in_sizes, int n_in,
                              void* d_out, int out_size)
{
    const float* x    = (const float*)d_in[0];
    const float* c    = (const float*)d_in[1];
    const int*   exx  = (const int*)  d_in[2];
    const int*   exlx = (const int*)  d_in[3];
    const int*   ecx  = (const int*)  d_in[4];
    const float* Wx   = (const float*)d_in[5];
    const float* bx   = (const float*)d_in[6];
    const float* Wc   = (const float*)d_in[7];
    const float* bc   = (const float*)d_in[8];
    const float* Wp   = (const float*)d_in[9];
    const float* bp   = (const float*)d_in[10];

    float* x_out = (float*)d_out;
    float* c_out = x_out + (size_t)N_X * 128;

    float *mxx, *mxlx, *mcx, *agg;
    cudaGetSymbolAddress((void**)&mxx,  g_mxx);
    cudaGetSymbolAddress((void**)&mxlx, g_mxlx);
    cudaGetSymbolAddress((void**)&mcx,  g_mcx);
    cudaGetSymbolAddress((void**)&agg,  g_agg);

    cudaFuncSetAttribute((const void*)gemm_kernel<128, true>,
                         cudaFuncAttributeMaxDynamicSharedMemorySize, SMEM_BYTES);
    cudaFuncSetAttribute((const void*)gemm_kernel<64, true>,
                         cudaFuncAttributeMaxDynamicSharedMemorySize, SMEM_BYTES);
    cudaFuncSetAttribute((const void*)gemm_kernel<128, false>,
                         cudaFuncAttributeMaxDynamicSharedMemorySize, SMEM_BYTES);

    const int gx = (N_X + BM - 1) / BM;   // 782

    // ex = relu(x@Wx+bx): cols 0:128 -> agg (self term), 128:256 -> mxx, 256:384 -> mxlx
    gemm_kernel<128, true><<<dim3(gx, 3), 256, SMEM_BYTES>>>(
        x, N_X, 128, Wx, 384, bx, agg, mxx, mxlx);

    // ec = relu(c@Wc+bc): cols 0:128 -> c_out, 128:256 -> mcx
    gemm_kernel<64, true><<<dim3(gx, 2), 256, SMEM_BYTES>>>(
        c, N_C, 64, Wc, 256, bc, c_out, mcx, nullptr);

    // edge scatter: 1.5M warps, 8 warps/block
    scatter_kernel<<<(3 * NE) / 8, 256>>>(exx, exlx, ecx);

    // x_out = agg@Wp + bp (no relu)
    gemm_kernel<128, false><<<dim3(gx, 1), 256, SMEM_BYTES>>>(
        agg, N_X, 128, Wp, 128, bp, x_out, nullptr, nullptr);
}

// round 5
// speedup vs baseline: 1.9919x; 1.9919x over previous
#include <cuda_runtime.h>
#include <cstdint>
#include <cstddef>

#define N_X 100000
#define N_C 100000
#define NE  500000
#define HID 128

// ---------------- scratch (__device__ globals per allocation rules) ----------------
__device__ float g_mxx [(size_t)N_X * HID];   // ex[:, H:2H]
__device__ float g_mxlx[(size_t)N_X * HID];   // ex[:, 2H:3H]
__device__ float g_mcx [(size_t)N_C * HID];   // ec[:, H:2H]
__device__ float g_agg [(size_t)N_X * HID];   // aggregate (init = ex[:, :H])
__device__ float g_WxT[384 * 128];            // Wx^T (K-major rows)
__device__ float g_WcT[256 * 64];             // Wc^T
__device__ float g_WpT[128 * 128];            // Wp^T

// ---------------- helpers ----------------------------------------------------------
__device__ __forceinline__ uint32_t f2tf32(float f) {
    uint32_t r;
    asm("cvt.rna.tf32.f32 %0, %1;" : "=r"(r) : "f"(f));
    return r;
}
__device__ __forceinline__ void mma_tf32(float* c, uint32_t a0, uint32_t a1,
                                         uint32_t a2, uint32_t a3,
                                         uint32_t b0, uint32_t b1) {
    asm volatile(
        "mma.sync.aligned.m16n8k8.row.col.f32.tf32.tf32.f32 "
        "{%0,%1,%2,%3}, {%4,%5,%6,%7}, {%8,%9}, {%0,%1,%2,%3};"
        : "+f"(c[0]), "+f"(c[1]), "+f"(c[2]), "+f"(c[3])
        : "r"(a0), "r"(a1), "r"(a2), "r"(a3), "r"(b0), "r"(b1));
}

// ---------------- tf32 mma.sync GEMM ----------------------------------------------
// D[M, 128] (chunk blockIdx.y) = relu?(A[M,K] @ BT[chunk*128 : , K]^T + bias_chunk)
// BM=128, BN=128, BK=64; 8 warps = 2(m) x 4(n); warp tile 64x32 (4x4 m16n8k8).
constexpr int PITCH = 68;   // floats; (4*g + tig) % 32 distinct -> conflict-free frags

template <int K, bool RELU>
__global__ __launch_bounds__(256)
void mma_gemm(const float* __restrict__ A, int M,
              const float* __restrict__ BT,
              const float* __restrict__ bias,
              float* __restrict__ o0, float* __restrict__ o1, float* __restrict__ o2)
{
    extern __shared__ float sm[];
    float* sBias = sm;                    // 128 floats
    float* sA    = sm + 128;              // [128][PITCH]
    float* sB    = sA + 128 * PITCH;      // [128][PITCH]

    const int tid  = threadIdx.x;
    const int wid  = tid >> 5;
    const int lane = tid & 31;
    const int g    = lane >> 2;           // group id (0..7)
    const int tig  = lane & 3;            // thread-in-group
    const int wm   = wid & 1;             // warp m (0..1) -> 64 rows
    const int wn   = wid >> 1;            // warp n (0..3) -> 32 cols
    const int rb   = blockIdx.x * 128;
    const int ntc  = blockIdx.y;          // 128-col chunk

    if (tid < 128) sBias[tid] = bias[ntc * 128 + tid];

    float acc[4][4][4];
#pragma unroll
    for (int mt = 0; mt < 4; mt++)
#pragma unroll
        for (int nt = 0; nt < 4; nt++)
#pragma unroll
            for (int j = 0; j < 4; j++) acc[mt][nt][j] = 0.f;

#pragma unroll 1
    for (int kt = 0; kt < K; kt += 64) {
        // A tile: 128 rows x 64 k (tf32-converted), zero-fill M tail
        for (int i = tid; i < 128 * 16; i += 256) {
            int r  = i >> 4;
            int cg = (i & 15) * 4;
            float4 v = make_float4(0.f, 0.f, 0.f, 0.f);
            if (rb + r < M)
                v = *reinterpret_cast<const float4*>(A + (size_t)(rb + r) * K + kt + cg);
            uint4 t = make_uint4(f2tf32(v.x), f2tf32(v.y), f2tf32(v.z), f2tf32(v.w));
            *reinterpret_cast<uint4*>(sA + r * PITCH + cg) = t;
        }
        // B tile: 128 n-rows x 64 k (BT is K-major: row n = B[:,n])
        const float* Bp = BT + (size_t)ntc * 128 * K + kt;
        for (int i = tid; i < 128 * 16; i += 256) {
            int r  = i >> 4;
            int cg = (i & 15) * 4;
            float4 v = *reinterpret_cast<const float4*>(Bp + (size_t)r * K + cg);
            uint4 t = make_uint4(f2tf32(v.x), f2tf32(v.y), f2tf32(v.z), f2tf32(v.w));
            *reinterpret_cast<uint4*>(sB + r * PITCH + cg) = t;
        }
        __syncthreads();

#pragma unroll
        for (int s = 0; s < 8; s++) {
            uint32_t bf[4][2];
#pragma unroll
            for (int nt = 0; nt < 4; nt++) {
                const float* p = sB + (wn * 32 + nt * 8 + g) * PITCH + s * 8 + tig;
                bf[nt][0] = __float_as_uint(p[0]);
                bf[nt][1] = __float_as_uint(p[4]);
            }
#pragma unroll
            for (int mt = 0; mt < 4; mt++) {
                const float* p = sA + (wm * 64 + mt * 16 + g) * PITCH + s * 8 + tig;
                uint32_t a0 = __float_as_uint(p[0]);
                uint32_t a1 = __float_as_uint(p[8 * PITCH]);
                uint32_t a2 = __float_as_uint(p[4]);
                uint32_t a3 = __float_as_uint(p[8 * PITCH + 4]);
#pragma unroll
                for (int nt = 0; nt < 4; nt++)
                    mma_tf32(acc[mt][nt], a0, a1, a2, a3, bf[nt][0], bf[nt][1]);
            }
        }
        __syncthreads();
    }

    // epilogue: bias + relu, direct global stores (float2 per fragment half)
    float* o = (ntc == 0) ? o0 : ((ntc == 1) ? o1 : o2);
#pragma unroll
    for (int mt = 0; mt < 4; mt++) {
        int row = rb + wm * 64 + mt * 16 + g;
#pragma unroll
        for (int nt = 0; nt < 4; nt++) {
            int col = wn * 32 + nt * 8 + 2 * tig;
            float b0 = sBias[col], b1 = sBias[col + 1];
            float v0 = acc[mt][nt][0] + b0, v1 = acc[mt][nt][1] + b1;
            float v2 = acc[mt][nt][2] + b0, v3 = acc[mt][nt][3] + b1;
            if (RELU) {
                v0 = fmaxf(v0, 0.f); v1 = fmaxf(v1, 0.f);
                v2 = fmaxf(v2, 0.f); v3 = fmaxf(v3, 0.f);
            }
            if (row < M)
                *reinterpret_cast<float2*>(o + (size_t)row * 128 + col) = make_float2(v0, v1);
            if (row + 8 < M)
                *reinterpret_cast<float2*>(o + (size_t)(row + 8) * 128 + col) = make_float2(v2, v3);
        }
    }
}

// ---------------- weight transpose: in[K,N] -> out[N,K] ----------------------------
__global__ void transpose_kernel(const float* __restrict__ in, float* __restrict__ out,
                                 int K, int N)
{
    int idx = blockIdx.x * blockDim.x + threadIdx.x;
    if (idx < K * N) {
        int k = idx / N, n = idx % N;
        out[n * K + k] = in[idx];
    }
}

// ---------------- scatter: one warp per edge, red.global.add.v4 --------------------
__global__ void scatter_kernel(const int* __restrict__ exx,
                               const int* __restrict__ exlx,
                               const int* __restrict__ ecx)
{
    int wid  = blockIdx.x * (blockDim.x >> 5) + (threadIdx.x >> 5);
    int lane = threadIdx.x & 31;
    if (wid >= 3 * NE) return;

    const float* src;
    int dst;
    if (wid < NE) {
        int e = wid;
        src = g_mxx + (size_t)exx[e] * HID;
        dst = exx[NE + e];
    } else if (wid < 2 * NE) {
        int e = wid - NE;
        src = g_mxlx + (size_t)exlx[NE + e] * HID;
        dst = exlx[e];
    } else {
        int e = wid - 2 * NE;
        src = g_mcx + (size_t)ecx[e] * HID;
        dst = ecx[NE + e];
    }

    float4 v = __ldg(reinterpret_cast<const float4*>(src) + lane);
    float* p = g_agg + (size_t)dst * HID + lane * 4;
    asm volatile("red.global.add.v4.f32 [%0], {%1, %2, %3, %4};"
                 :: "l"(p), "f"(v.x), "f"(v.y), "f"(v.z), "f"(v.w)
                 : "memory");
}

// ---------------- launch -----------------------------------------------------------
extern "C" void kernel_launch(void* const* d_in, const int* in_sizes, int n_in,
                              void* d_out, int out_size)
{
    const float* x    = (const float*)d_in[0];
    const float* c    = (const float*)d_in[1];
    const int*   exx  = (const int*)  d_in[2];
    const int*   exlx = (const int*)  d_in[3];
    const int*   ecx  = (const int*)  d_in[4];
    const float* Wx   = (const float*)d_in[5];
    const float* bx   = (const float*)d_in[6];
    const float* Wc   = (const float*)d_in[7];
    const float* bc   = (const float*)d_in[8];
    const float* Wp   = (const float*)d_in[9];
    const float* bp   = (const float*)d_in[10];

    float* x_out = (float*)d_out;
    float* c_out = x_out + (size_t)N_X * 128;

    float *mxx, *mxlx, *mcx, *agg, *WxT, *WcT, *WpT;
    cudaGetSymbolAddress((void**)&mxx,  g_mxx);
    cudaGetSymbolAddress((void**)&mxlx, g_mxlx);
    cudaGetSymbolAddress((void**)&mcx,  g_mcx);
    cudaGetSymbolAddress((void**)&agg,  g_agg);
    cudaGetSymbolAddress((void**)&WxT,  g_WxT);
    cudaGetSymbolAddress((void**)&WcT,  g_WcT);
    cudaGetSymbolAddress((void**)&WpT,  g_WpT);

    constexpr int SMEM = (128 + 2 * 128 * PITCH) * 4;   // 70144 bytes

    cudaFuncSetAttribute((const void*)mma_gemm<128, true>,
                         cudaFuncAttributeMaxDynamicSharedMemorySize, SMEM);
    cudaFuncSetAttribute((const void*)mma_gemm<64, true>,
                         cudaFuncAttributeMaxDynamicSharedMemorySize, SMEM);
    cudaFuncSetAttribute((const void*)mma_gemm<128, false>,
                         cudaFuncAttributeMaxDynamicSharedMemorySize, SMEM);

    // weight transposes (tiny)
    transpose_kernel<<<(128 * 384 + 255) / 256, 256>>>(Wx, WxT, 128, 384);
    transpose_kernel<<<(64  * 256 + 255) / 256, 256>>>(Wc, WcT, 64, 256);
    transpose_kernel<<<(128 * 128 + 255) / 256, 256>>>(Wp, WpT, 128, 128);

    const int gx = (N_X + 127) / 128;   // 782

    // ex = relu(x@Wx+bx): chunk 0 -> agg (self term), 1 -> mxx, 2 -> mxlx
    mma_gemm<128, true><<<dim3(gx, 3), 256, SMEM>>>(x, N_X, WxT, bx, agg, mxx, mxlx);

    // ec = relu(c@Wc+bc): chunk 0 -> c_out, 1 -> mcx
    mma_gemm<64, true><<<dim3(gx, 2), 256, SMEM>>>(c, N_C, WcT, bc, c_out, mcx, nullptr);

    // edge scatter
    scatter_kernel<<<(3 * NE) / 8, 256>>>(exx, exlx, ecx);

    // x_out = agg@Wp + bp
    mma_gemm<128, false><<<dim3(gx, 1), 256, SMEM>>>(agg, N_X, WpT, bp, x_out, nullptr, nullptr);
}